// round 10
// baseline (speedup 1.0000x reference)
#include <cuda_runtime.h>
#include <cuda_bf16.h>
#include <cstdint>

#define CI  256   // channels
#define II  16    // irrep dim
#define NK3 23
#define NK2 4
#define NT3 816   // C(18,3) sorted triples p<=q<=j
#define NT2 136   // sorted pairs p<=q
#define NCOEFF (NT3 + NT2 + II)   // 968
#define BMAX 4096

// ---------------- static device scratch (no allocation allowed) ----------------
__device__ float              g_P[NT3 * NK3];          // symmetrized U3 basis
__device__ unsigned long long g_coeff[CI * 1024];      // per-channel packed (v,v) coeffs
__device__ float              g_out1T[CI * BMAX];      // (C, B) transposed intermediate
// bf16x3-split GEMM operands, packed (k_even, k_odd) bf16x2 per u32, layout [k/2][m|n]
__device__ unsigned int       gAh[(CI / 2) * BMAX];    // 2 MB
__device__ unsigned int       gAl[(CI / 2) * BMAX];    // 2 MB
__device__ unsigned int       gBh[(CI / 2) * CI];      // 128 KB
__device__ unsigned int       gBl[(CI / 2) * CI];      // 128 KB

typedef unsigned long long ull;

// ---------------- f32x2 packed-math helpers (sm_103a FFMA2 path) ----------------
__device__ __forceinline__ ull pk2(float lo, float hi) {
    ull r;
    asm("mov.b64 %0, {%1, %2};" : "=l"(r) : "f"(lo), "f"(hi));
    return r;
}
__device__ __forceinline__ void upk2(ull v, float& lo, float& hi) {
    asm("mov.b64 {%0, %1}, %2;" : "=f"(lo), "=f"(hi) : "l"(v));
}
__device__ __forceinline__ ull fma2(ull a, ull b, ull c) {
    ull d;
    asm("fma.rn.f32x2 %0, %1, %2, %3;" : "=l"(d) : "l"(a), "l"(b), "l"(c));
    return d;
}

// ---------------- bf16 helpers ----------------
__device__ __forceinline__ unsigned int packbf(float v0, float v1,
                                               float& r0, float& r1) {
    __nv_bfloat16 h0 = __float2bfloat16_rn(v0);
    __nv_bfloat16 h1 = __float2bfloat16_rn(v1);
    r0 = v0 - __bfloat162float(h0);
    r1 = v1 - __bfloat162float(h1);
    unsigned short u0 = *reinterpret_cast<unsigned short*>(&h0);
    unsigned short u1 = *reinterpret_cast<unsigned short*>(&h1);
    return (unsigned int)u0 | ((unsigned int)u1 << 16);
}
__device__ __forceinline__ unsigned int packbf_only(float v0, float v1) {
    __nv_bfloat16 h0 = __float2bfloat16_rn(v0);
    __nv_bfloat16 h1 = __float2bfloat16_rn(v1);
    unsigned short u0 = *reinterpret_cast<unsigned short*>(&h0);
    unsigned short u1 = *reinterpret_cast<unsigned short*>(&h1);
    return (unsigned int)u0 | ((unsigned int)u1 << 16);
}

// mma.sync m16n8k16 bf16 (fallback HMMA on sm_103a)
__device__ __forceinline__ void mma_bf16(float* c, const unsigned int* a,
                                         const unsigned int* b) {
    asm volatile(
        "mma.sync.aligned.m16n8k16.row.col.f32.bf16.bf16.f32 "
        "{%0,%1,%2,%3}, {%4,%5,%6,%7}, {%8,%9}, {%0,%1,%2,%3};"
        : "+f"(c[0]), "+f"(c[1]), "+f"(c[2]), "+f"(c[3])
        : "r"(a[0]), "r"(a[1]), "r"(a[2]), "r"(a[3]), "r"(b[0]), "r"(b[1]));
}

// ---------------- P0: symmetrize U3 over permutations -> g_P[t][k] ----------------
#define U3AT(a, b, d) U3[((((a) * II + (b)) * II + (d)) * NK3) + k]

__global__ void p0_kernel(const float* __restrict__ U3) {
    int idx = blockIdx.x * blockDim.x + threadIdx.x;
    if (idx >= NT3 * NK3) return;
    int t = idx / NK3, k = idx - t * NK3;
    int p = 0, rem = t;
    while (rem >= (II - p) * (II - p + 1) / 2) { rem -= (II - p) * (II - p + 1) / 2; p++; }
    int q = p;
    while (rem >= II - q) { rem -= II - q; q++; }
    int j = q + rem;

    float s;
    if (p == q && q == j) {
        s = U3AT(p, p, p);
    } else if (p == q) {
        s = U3AT(p, p, j) + U3AT(p, j, p) + U3AT(j, p, p);
    } else if (q == j) {
        s = U3AT(p, q, q) + U3AT(q, p, q) + U3AT(q, q, p);
    } else {
        s = U3AT(p, q, j) + U3AT(p, j, q) + U3AT(q, p, j) +
            U3AT(q, j, p) + U3AT(j, p, q) + U3AT(j, q, p);
    }
    g_P[t * NK3 + k] = s;
}

// ---------------- P1: per-channel coefficient build (compact layout) ----------------
__global__ void p1_kernel(const float* __restrict__ U2, const float* __restrict__ U1,
                          const float* __restrict__ w3, const float* __restrict__ w2,
                          const float* __restrict__ w1) {
    int c = blockIdx.x;
    int tid = threadIdx.x;
    __shared__ float w3s[NK3];
    __shared__ float w2s[NK2];
    __shared__ float w1s;
    if (tid < NK3) w3s[tid] = w3[c * NK3 + tid];
    if (tid < NK2) w2s[tid] = w2[c * NK2 + tid];
    if (tid == 0)  w1s = w1[c];
    __syncthreads();

    ull* cc = g_coeff + (size_t)c * 1024;

    for (int t = tid; t < NT3; t += blockDim.x) {
        float s = 0.f;
#pragma unroll
        for (int k = 0; k < NK3; k++) s += g_P[t * NK3 + k] * w3s[k];
        cc[t] = pk2(s, s);
    }
    for (int u = tid; u < NT2; u += blockDim.x) {
        int p = 0, rem = u;
        while (rem >= II - p) { rem -= II - p; p++; }
        int q = p + rem;
        float s = 0.f;
#pragma unroll
        for (int k = 0; k < NK2; k++) {
            float v = (p == q) ? U2[(p * II + p) * NK2 + k]
                               : (U2[(p * II + q) * NK2 + k] + U2[(q * II + p) * NK2 + k]);
            s += w2s[k] * v;
        }
        cc[NT3 + u] = pk2(s, s);
    }
    for (int p = tid; p < II; p += blockDim.x) {
        float s = U1[p] * w1s;  // K1 == 1
        cc[NT3 + NT2 + p] = pk2(s, s);
    }
}

// ---------------- Main: factored symmetric contraction, staged x, 4 b's/thread ----------------
#define XPAD 524
__global__ __launch_bounds__(128, 4) void main_kernel(const float* __restrict__ nf) {
    __shared__ ull   sco[NCOEFF];           // 7.75 KB
    __shared__ float xs[II][XPAD];          // 33.5 KB transposed x tile (512 b's)
    int c = blockIdx.y;
    int tid = threadIdx.x;
    {
        const ull* cc = g_coeff + (size_t)c * 1024;
        for (int i = tid; i < NCOEFF; i += 128) sco[i] = cc[i];
    }
    int bbase = blockIdx.x * 512;

#pragma unroll
    for (int it = 0; it < 16; it++) {
        int f = it * 128 + tid;
        int r = f >> 2, qd = f & 3;
        float4 v = *reinterpret_cast<const float4*>(
            &nf[((size_t)(bbase + r) * CI + c) * II + qd * 4]);
        xs[qd * 4 + 0][r] = v.x;
        xs[qd * 4 + 1][r] = v.y;
        xs[qd * 4 + 2][r] = v.z;
        xs[qd * 4 + 3][r] = v.w;
    }
    __syncthreads();

    int t4 = tid * 4;
    ull xA[II], xB[II];
#pragma unroll
    for (int i = 0; i < II; i++) {
        float4 v = *reinterpret_cast<const float4*>(&xs[i][t4]);
        xA[i] = pk2(v.x, v.y);
        xB[i] = pk2(v.z, v.w);
    }

    ull accA = 0ull, accB = 0ull;
    int s = 0, u = 0;
#pragma unroll
    for (int p = 0; p < II; p++) {
        ull c1v = sco[NT3 + NT2 + p];
        ull innerA = c1v, innerB = c1v;
#pragma unroll
        for (int q = p; q < II; q++) {
            ull c2v = sco[NT3 + u]; u++;
            ull pA = c2v, pB = c2v;
#pragma unroll
            for (int j = q; j < II; j++) {
                ull sv = sco[s]; s++;
                pA = fma2(xA[j], sv, pA);
                pB = fma2(xB[j], sv, pB);
            }
            innerA = fma2(xA[q], pA, innerA);
            innerB = fma2(xB[q], pB, innerB);
        }
        accA = fma2(xA[p], innerA, accA);
        accB = fma2(xB[p], innerB, accB);
    }

    float r0, r1, r2, r3;
    upk2(accA, r0, r1);
    upk2(accB, r2, r3);
    *reinterpret_cast<float4*>(&g_out1T[(size_t)c * BMAX + bbase + t4]) =
        make_float4(r0, r1, r2, r3);
}

// ---------------- convA: g_out1T (k-major f32) -> packed bf16 hi/lo [k/2][m] ----------------
__global__ __launch_bounds__(256) void convA_kernel() {
    int m = blockIdx.x * 256 + threadIdx.x;
    int k2 = blockIdx.y;
    float v0 = g_out1T[(size_t)(2 * k2) * BMAX + m];
    float v1 = g_out1T[(size_t)(2 * k2 + 1) * BMAX + m];
    float r0, r1;
    unsigned int hi = packbf(v0, v1, r0, r1);
    unsigned int lo = packbf_only(r0, r1);
    gAh[(size_t)k2 * BMAX + m] = hi;
    gAl[(size_t)k2 * BMAX + m] = lo;
}

// ---------------- convB: W (k-major f32) -> packed bf16 hi/lo [k/2][n] ----------------
__global__ __launch_bounds__(256) void convB_kernel(const float* __restrict__ W) {
    int n = threadIdx.x;
    int k2 = blockIdx.x;
    float v0 = W[(size_t)(2 * k2) * CI + n];
    float v1 = W[(size_t)(2 * k2 + 1) * CI + n];
    float r0, r1;
    unsigned int hi = packbf(v0, v1, r0, r1);
    unsigned int lo = packbf_only(r0, r1);
    gBh[(size_t)k2 * CI + n] = hi;
    gBl[(size_t)k2 * CI + n] = lo;
}

// ---------------- o3.Linear via mma.sync bf16x3: 64m x 64n CTA, 64m x 16n warps ----------------
__global__ __launch_bounds__(128) void lin_mma_kernel(float* __restrict__ O) {
    int tid = threadIdx.x;
    int lane = tid & 31, wid = tid >> 5;
    int mb = blockIdx.x * 64;
    int nb = blockIdx.y * 64 + wid * 16;
    int gid = lane >> 2;      // 0..7
    int tig = lane & 3;       // 0..3

    float acc[4][2][4] = {};  // [mblk][nblk][frag]

    for (int k0 = 0; k0 < CI; k0 += 16) {
        int k2b = k0 >> 1;
        // B fragments for this warp's 16 n-columns
        unsigned int bh[2][2], bl[2][2];
#pragma unroll
        for (int nblk = 0; nblk < 2; nblk++) {
            int n = nb + nblk * 8 + gid;
            bh[nblk][0] = gBh[(size_t)(k2b + tig) * CI + n];
            bh[nblk][1] = gBh[(size_t)(k2b + 4 + tig) * CI + n];
            bl[nblk][0] = gBl[(size_t)(k2b + tig) * CI + n];
            bl[nblk][1] = gBl[(size_t)(k2b + 4 + tig) * CI + n];
        }
#pragma unroll
        for (int mblk = 0; mblk < 4; mblk++) {
            int m = mb + mblk * 16 + gid;
            unsigned int ah[4], al[4];
            ah[0] = gAh[(size_t)(k2b + tig) * BMAX + m];
            ah[1] = gAh[(size_t)(k2b + tig) * BMAX + m + 8];
            ah[2] = gAh[(size_t)(k2b + 4 + tig) * BMAX + m];
            ah[3] = gAh[(size_t)(k2b + 4 + tig) * BMAX + m + 8];
            al[0] = gAl[(size_t)(k2b + tig) * BMAX + m];
            al[1] = gAl[(size_t)(k2b + tig) * BMAX + m + 8];
            al[2] = gAl[(size_t)(k2b + 4 + tig) * BMAX + m];
            al[3] = gAl[(size_t)(k2b + 4 + tig) * BMAX + m + 8];
#pragma unroll
            for (int nblk = 0; nblk < 2; nblk++) {
                mma_bf16(acc[mblk][nblk], ah, bh[nblk]);   // hi*hi
                mma_bf16(acc[mblk][nblk], ah, bl[nblk]);   // hi*lo
                mma_bf16(acc[mblk][nblk], al, bh[nblk]);   // lo*hi
            }
        }
    }

    const float inv = 0.0625f;   // 1/sqrt(256)
#pragma unroll
    for (int mblk = 0; mblk < 4; mblk++) {
#pragma unroll
        for (int nblk = 0; nblk < 2; nblk++) {
            int m = mb + mblk * 16 + gid;
            int n = nb + nblk * 8 + tig * 2;
            *reinterpret_cast<float2*>(&O[(size_t)m * CI + n]) =
                make_float2(acc[mblk][nblk][0] * inv, acc[mblk][nblk][1] * inv);
            *reinterpret_cast<float2*>(&O[(size_t)(m + 8) * CI + n]) =
                make_float2(acc[mblk][nblk][2] * inv, acc[mblk][nblk][3] * inv);
        }
    }
}

// ---------------- launch ----------------
extern "C" void kernel_launch(void* const* d_in, const int* in_sizes, int n_in,
                              void* d_out, int out_size) {
    const float* nf = (const float*)d_in[0];
    const float* U3 = (const float*)d_in[1];
    const float* U2 = (const float*)d_in[2];
    const float* U1 = (const float*)d_in[3];
    const float* w3 = (const float*)d_in[4];
    const float* w2 = (const float*)d_in[5];
    const float* w1 = (const float*)d_in[6];
    const float* WL = (const float*)d_in[7];
    float* out = (float*)d_out;

    int B = in_sizes[0] / (CI * II);   // 4096

    p0_kernel<<<(NT3 * NK3 + 255) / 256, 256>>>(U3);
    p1_kernel<<<CI, 128>>>(U2, U1, w3, w2, w1);
    convB_kernel<<<CI / 2, 256>>>(WL);                       // independent of main
    main_kernel<<<dim3(B / 512, CI), 128>>>(nf);
    convA_kernel<<<dim3(B / 256, CI / 2), 256>>>();
    lin_mma_kernel<<<dim3(B / 64, CI / 64), 128>>>(out);
}

// round 11
// speedup vs baseline: 1.0417x; 1.0417x over previous
#include <cuda_runtime.h>
#include <cuda_bf16.h>
#include <cstdint>

#define CI  256   // channels
#define II  16    // irrep dim
#define NK3 23
#define NK2 4
#define NT3 816   // C(18,3) sorted triples p<=q<=j
#define NT2 136   // sorted pairs p<=q
#define NCOEFF (NT3 + NT2 + II)   // 968
#define BMAX 4096

// ---------------- static device scratch (no allocation allowed) ----------------
__device__ float              g_P[NT3 * NK3];          // symmetrized U3 basis
__device__ unsigned long long g_coeff[CI * 1024];      // per-channel packed (v,v) coeffs
__device__ float              g_out1T[CI * BMAX];      // (C, B) transposed intermediate
// bf16x3-split GEMM operands, packed (k_even, k_odd) bf16x2 per u32, layout [k/2][m|n]
__device__ unsigned int       gAh[(CI / 2) * BMAX];
__device__ unsigned int       gAl[(CI / 2) * BMAX];
__device__ unsigned int       gBh[(CI / 2) * CI];
__device__ unsigned int       gBl[(CI / 2) * CI];

typedef unsigned long long ull;

// ---------------- f32x2 packed-math helpers ----------------
__device__ __forceinline__ ull pk2(float lo, float hi) {
    ull r;
    asm("mov.b64 %0, {%1, %2};" : "=l"(r) : "f"(lo), "f"(hi));
    return r;
}
__device__ __forceinline__ void upk2(ull v, float& lo, float& hi) {
    asm("mov.b64 {%0, %1}, %2;" : "=f"(lo), "=f"(hi) : "l"(v));
}
__device__ __forceinline__ ull fma2(ull a, ull b, ull c) {
    ull d;
    asm("fma.rn.f32x2 %0, %1, %2, %3;" : "=l"(d) : "l"(a), "l"(b), "l"(c));
    return d;
}

// ---------------- bf16 helpers ----------------
__device__ __forceinline__ unsigned int packbf(float v0, float v1,
                                               float& r0, float& r1) {
    __nv_bfloat16 h0 = __float2bfloat16_rn(v0);
    __nv_bfloat16 h1 = __float2bfloat16_rn(v1);
    r0 = v0 - __bfloat162float(h0);
    r1 = v1 - __bfloat162float(h1);
    unsigned short u0 = *reinterpret_cast<unsigned short*>(&h0);
    unsigned short u1 = *reinterpret_cast<unsigned short*>(&h1);
    return (unsigned int)u0 | ((unsigned int)u1 << 16);
}
__device__ __forceinline__ unsigned int packbf_only(float v0, float v1) {
    __nv_bfloat16 h0 = __float2bfloat16_rn(v0);
    __nv_bfloat16 h1 = __float2bfloat16_rn(v1);
    unsigned short u0 = *reinterpret_cast<unsigned short*>(&h0);
    unsigned short u1 = *reinterpret_cast<unsigned short*>(&h1);
    return (unsigned int)u0 | ((unsigned int)u1 << 16);
}

// mma.sync m16n8k16 bf16
__device__ __forceinline__ void mma_bf16(float* c, const unsigned int* a,
                                         const unsigned int* b) {
    asm volatile(
        "mma.sync.aligned.m16n8k16.row.col.f32.bf16.bf16.f32 "
        "{%0,%1,%2,%3}, {%4,%5,%6,%7}, {%8,%9}, {%0,%1,%2,%3};"
        : "+f"(c[0]), "+f"(c[1]), "+f"(c[2]), "+f"(c[3])
        : "r"(a[0]), "r"(a[1]), "r"(a[2]), "r"(a[3]), "r"(b[0]), "r"(b[1]));
}

// ---------------- P0: symmetrize U3 over permutations -> g_P[t][k] ----------------
#define U3AT(a, b, d) U3[((((a) * II + (b)) * II + (d)) * NK3) + k]

__global__ void p0_kernel(const float* __restrict__ U3) {
    int idx = blockIdx.x * blockDim.x + threadIdx.x;
    if (idx >= NT3 * NK3) return;
    int t = idx / NK3, k = idx - t * NK3;
    int p = 0, rem = t;
    while (rem >= (II - p) * (II - p + 1) / 2) { rem -= (II - p) * (II - p + 1) / 2; p++; }
    int q = p;
    while (rem >= II - q) { rem -= II - q; q++; }
    int j = q + rem;

    float s;
    if (p == q && q == j) {
        s = U3AT(p, p, p);
    } else if (p == q) {
        s = U3AT(p, p, j) + U3AT(p, j, p) + U3AT(j, p, p);
    } else if (q == j) {
        s = U3AT(p, q, q) + U3AT(q, p, q) + U3AT(q, q, p);
    } else {
        s = U3AT(p, q, j) + U3AT(p, j, q) + U3AT(q, p, j) +
            U3AT(q, j, p) + U3AT(j, p, q) + U3AT(j, q, p);
    }
    g_P[t * NK3 + k] = s;
}

// ---------------- P1: per-channel coefficient build ----------------
__global__ void p1_kernel(const float* __restrict__ U2, const float* __restrict__ U1,
                          const float* __restrict__ w3, const float* __restrict__ w2,
                          const float* __restrict__ w1) {
    int c = blockIdx.x;
    int tid = threadIdx.x;
    __shared__ float w3s[NK3];
    __shared__ float w2s[NK2];
    __shared__ float w1s;
    if (tid < NK3) w3s[tid] = w3[c * NK3 + tid];
    if (tid < NK2) w2s[tid] = w2[c * NK2 + tid];
    if (tid == 0)  w1s = w1[c];
    __syncthreads();

    ull* cc = g_coeff + (size_t)c * 1024;

    for (int t = tid; t < NT3; t += blockDim.x) {
        float s = 0.f;
#pragma unroll
        for (int k = 0; k < NK3; k++) s += g_P[t * NK3 + k] * w3s[k];
        cc[t] = pk2(s, s);
    }
    for (int u = tid; u < NT2; u += blockDim.x) {
        int p = 0, rem = u;
        while (rem >= II - p) { rem -= II - p; p++; }
        int q = p + rem;
        float s = 0.f;
#pragma unroll
        for (int k = 0; k < NK2; k++) {
            float v = (p == q) ? U2[(p * II + p) * NK2 + k]
                               : (U2[(p * II + q) * NK2 + k] + U2[(q * II + p) * NK2 + k]);
            s += w2s[k] * v;
        }
        cc[NT3 + u] = pk2(s, s);
    }
    for (int p = tid; p < II; p += blockDim.x) {
        float s = U1[p] * w1s;  // K1 == 1
        cc[NT3 + NT2 + p] = pk2(s, s);
    }
}

// ---------------- Main: factored symmetric contraction, staged x, 4 b's/thread ----------------
#define XPAD 524
__global__ __launch_bounds__(128, 5) void main_kernel(const float* __restrict__ nf) {
    __shared__ ull   sco[NCOEFF];           // 7.75 KB
    __shared__ float xs[II][XPAD];          // 33.5 KB transposed x tile (512 b's)
    int c = blockIdx.y;
    int tid = threadIdx.x;
    {
        const ull* cc = g_coeff + (size_t)c * 1024;
        for (int i = tid; i < NCOEFF; i += 128) sco[i] = cc[i];
    }
    int bbase = blockIdx.x * 512;

#pragma unroll
    for (int it = 0; it < 16; it++) {
        int f = it * 128 + tid;
        int r = f >> 2, qd = f & 3;
        float4 v = *reinterpret_cast<const float4*>(
            &nf[((size_t)(bbase + r) * CI + c) * II + qd * 4]);
        xs[qd * 4 + 0][r] = v.x;
        xs[qd * 4 + 1][r] = v.y;
        xs[qd * 4 + 2][r] = v.z;
        xs[qd * 4 + 3][r] = v.w;
    }
    __syncthreads();

    int t4 = tid * 4;
    ull xA[II], xB[II];
#pragma unroll
    for (int i = 0; i < II; i++) {
        float4 v = *reinterpret_cast<const float4*>(&xs[i][t4]);
        xA[i] = pk2(v.x, v.y);
        xB[i] = pk2(v.z, v.w);
    }

    ull accA = 0ull, accB = 0ull;
    int s = 0, u = 0;
#pragma unroll
    for (int p = 0; p < II; p++) {
        ull c1v = sco[NT3 + NT2 + p];
        ull innerA = c1v, innerB = c1v;
#pragma unroll
        for (int q = p; q < II; q++) {
            ull c2v = sco[NT3 + u]; u++;
            ull pA = c2v, pB = c2v;
#pragma unroll
            for (int j = q; j < II; j++) {
                ull sv = sco[s]; s++;
                pA = fma2(xA[j], sv, pA);
                pB = fma2(xB[j], sv, pB);
            }
            innerA = fma2(xA[q], pA, innerA);
            innerB = fma2(xB[q], pB, innerB);
        }
        accA = fma2(xA[p], innerA, accA);
        accB = fma2(xB[p], innerB, accB);
    }

    float r0, r1, r2, r3;
    upk2(accA, r0, r1);
    upk2(accB, r2, r3);
    *reinterpret_cast<float4*>(&g_out1T[(size_t)c * BMAX + bbase + t4]) =
        make_float4(r0, r1, r2, r3);
}

// ---------------- convA: g_out1T (k-major f32) -> packed bf16 hi/lo [k/2][m] ----------------
__global__ __launch_bounds__(256) void convA_kernel() {
    int m = blockIdx.x * 256 + threadIdx.x;
    int k2 = blockIdx.y;
    float v0 = g_out1T[(size_t)(2 * k2) * BMAX + m];
    float v1 = g_out1T[(size_t)(2 * k2 + 1) * BMAX + m];
    float r0, r1;
    unsigned int hi = packbf(v0, v1, r0, r1);
    unsigned int lo = packbf_only(r0, r1);
    gAh[(size_t)k2 * BMAX + m] = hi;
    gAl[(size_t)k2 * BMAX + m] = lo;
}

// ---------------- convB: W (k-major f32) -> packed bf16 hi/lo [k/2][n] ----------------
__global__ __launch_bounds__(256) void convB_kernel(const float* __restrict__ W) {
    int n = threadIdx.x;
    int k2 = blockIdx.x;
    float v0 = W[(size_t)(2 * k2) * CI + n];
    float v1 = W[(size_t)(2 * k2 + 1) * CI + n];
    float r0, r1;
    unsigned int hi = packbf(v0, v1, r0, r1);
    unsigned int lo = packbf_only(r0, r1);
    gBh[(size_t)k2 * CI + n] = hi;
    gBl[(size_t)k2 * CI + n] = lo;
}

// ---------------- o3.Linear via mma.sync bf16x3: 32m x 32n CTA, 32m x 8n warps ----------------
__global__ __launch_bounds__(128) void lin_mma_kernel(float* __restrict__ O) {
    int tid = threadIdx.x;
    int lane = tid & 31, wid = tid >> 5;
    int mb = blockIdx.x * 32;
    int nb = blockIdx.y * 32 + wid * 8;
    int gid = lane >> 2;      // 0..7
    int tig = lane & 3;       // 0..3

    float acc[2][4] = {};     // [mblk][frag]

    for (int k0 = 0; k0 < CI; k0 += 16) {
        int k2b = k0 >> 1;
        // B fragments for this warp's 8 n-columns
        unsigned int bh[2], bl[2];
        {
            int n = nb + gid;
            bh[0] = gBh[(size_t)(k2b + tig) * CI + n];
            bh[1] = gBh[(size_t)(k2b + 4 + tig) * CI + n];
            bl[0] = gBl[(size_t)(k2b + tig) * CI + n];
            bl[1] = gBl[(size_t)(k2b + 4 + tig) * CI + n];
        }
#pragma unroll
        for (int mblk = 0; mblk < 2; mblk++) {
            int m = mb + mblk * 16 + gid;
            unsigned int ah[4], al[4];
            ah[0] = gAh[(size_t)(k2b + tig) * BMAX + m];
            ah[1] = gAh[(size_t)(k2b + tig) * BMAX + m + 8];
            ah[2] = gAh[(size_t)(k2b + 4 + tig) * BMAX + m];
            ah[3] = gAh[(size_t)(k2b + 4 + tig) * BMAX + m + 8];
            al[0] = gAl[(size_t)(k2b + tig) * BMAX + m];
            al[1] = gAl[(size_t)(k2b + tig) * BMAX + m + 8];
            al[2] = gAl[(size_t)(k2b + 4 + tig) * BMAX + m];
            al[3] = gAl[(size_t)(k2b + 4 + tig) * BMAX + m + 8];
            mma_bf16(acc[mblk], ah, bh);   // hi*hi
            mma_bf16(acc[mblk], ah, bl);   // hi*lo
            mma_bf16(acc[mblk], al, bh);   // lo*hi
        }
    }

    const float inv = 0.0625f;   // 1/sqrt(256)
#pragma unroll
    for (int mblk = 0; mblk < 2; mblk++) {
        int m = mb + mblk * 16 + gid;
        int n = nb + tig * 2;
        *reinterpret_cast<float2*>(&O[(size_t)m * CI + n]) =
            make_float2(acc[mblk][0] * inv, acc[mblk][1] * inv);
        *reinterpret_cast<float2*>(&O[(size_t)(m + 8) * CI + n]) =
            make_float2(acc[mblk][2] * inv, acc[mblk][3] * inv);
    }
}

// ---------------- launch ----------------
extern "C" void kernel_launch(void* const* d_in, const int* in_sizes, int n_in,
                              void* d_out, int out_size) {
    const float* nf = (const float*)d_in[0];
    const float* U3 = (const float*)d_in[1];
    const float* U2 = (const float*)d_in[2];
    const float* U1 = (const float*)d_in[3];
    const float* w3 = (const float*)d_in[4];
    const float* w2 = (const float*)d_in[5];
    const float* w1 = (const float*)d_in[6];
    const float* WL = (const float*)d_in[7];
    float* out = (float*)d_out;

    int B = in_sizes[0] / (CI * II);   // 4096

    p0_kernel<<<(NT3 * NK3 + 255) / 256, 256>>>(U3);
    p1_kernel<<<CI, 128>>>(U2, U1, w3, w2, w1);
    convB_kernel<<<CI / 2, 256>>>(WL);                       // independent of main
    main_kernel<<<dim3(B / 512, CI), 128>>>(nf);
    convA_kernel<<<dim3(B / 256, CI / 2), 256>>>();
    lin_mma_kernel<<<dim3(B / 32, CI / 32), 128>>>(out);
}

// round 13
// speedup vs baseline: 1.2217x; 1.1728x over previous
#include <cuda_runtime.h>
#include <cuda_bf16.h>
#include <cstdint>

#define CI  256   // channels
#define II  16    // irrep dim
#define NK3 23
#define NK2 4
#define NT3 816   // C(18,3) sorted triples p<=q<=j
#define NT2 136   // sorted pairs p<=q
#define NCOEFF (NT3 + NT2 + II)   // 968
#define BMAX 4096

// ---------------- static device scratch (no allocation allowed) ----------------
__device__ float              g_P[NT3 * NK3];          // symmetrized U3 basis
__device__ unsigned long long g_coeff[CI * 1024];      // per-channel packed (v,v) coeffs
__device__ float              g_out1T[CI * BMAX];      // (C, B) transposed intermediate
// mma-fragment-ordered operands (bf16x3 split):
// gAF: per (kt, mt): [hi 32 lanes x 4 u32][lo 32 lanes x 4 u32]  -> 16*256*256 u32 = 4 MB
// gBF: per (kt, nt): [hi 32 lanes x 2 u32][lo 32 lanes x 2 u32]  -> 16*32*128 u32 = 256 KB
__device__ unsigned int       gAF[16 * 256 * 256];
__device__ unsigned int       gBF[16 * 32 * 128];

typedef unsigned long long ull;

// ---------------- f32x2 packed-math helpers ----------------
__device__ __forceinline__ ull pk2(float lo, float hi) {
    ull r;
    asm("mov.b64 %0, {%1, %2};" : "=l"(r) : "f"(lo), "f"(hi));
    return r;
}
__device__ __forceinline__ void upk2(ull v, float& lo, float& hi) {
    asm("mov.b64 {%0, %1}, %2;" : "=f"(lo), "=f"(hi) : "l"(v));
}
__device__ __forceinline__ ull fma2(ull a, ull b, ull c) {
    ull d;
    asm("fma.rn.f32x2 %0, %1, %2, %3;" : "=l"(d) : "l"(a), "l"(b), "l"(c));
    return d;
}

// ---------------- bf16 helpers ----------------
__device__ __forceinline__ unsigned int packbf(float v0, float v1,
                                               float& r0, float& r1) {
    __nv_bfloat16 h0 = __float2bfloat16_rn(v0);
    __nv_bfloat16 h1 = __float2bfloat16_rn(v1);
    r0 = v0 - __bfloat162float(h0);
    r1 = v1 - __bfloat162float(h1);
    unsigned short u0 = *reinterpret_cast<unsigned short*>(&h0);
    unsigned short u1 = *reinterpret_cast<unsigned short*>(&h1);
    return (unsigned int)u0 | ((unsigned int)u1 << 16);
}
__device__ __forceinline__ unsigned int packbf_only(float v0, float v1) {
    __nv_bfloat16 h0 = __float2bfloat16_rn(v0);
    __nv_bfloat16 h1 = __float2bfloat16_rn(v1);
    unsigned short u0 = *reinterpret_cast<unsigned short*>(&h0);
    unsigned short u1 = *reinterpret_cast<unsigned short*>(&h1);
    return (unsigned int)u0 | ((unsigned int)u1 << 16);
}

// mma.sync m16n8k16 bf16
__device__ __forceinline__ void mma_bf16(float* c, const unsigned int* a,
                                         const unsigned int* b) {
    asm volatile(
        "mma.sync.aligned.m16n8k16.row.col.f32.bf16.bf16.f32 "
        "{%0,%1,%2,%3}, {%4,%5,%6,%7}, {%8,%9}, {%0,%1,%2,%3};"
        : "+f"(c[0]), "+f"(c[1]), "+f"(c[2]), "+f"(c[3])
        : "r"(a[0]), "r"(a[1]), "r"(a[2]), "r"(a[3]), "r"(b[0]), "r"(b[1]));
}

// ---------------- P0: symmetrize U3 over permutations -> g_P[t][k] ----------------
#define U3AT(a, b, d) U3[((((a) * II + (b)) * II + (d)) * NK3) + k]

__global__ void p0_kernel(const float* __restrict__ U3) {
    int idx = blockIdx.x * blockDim.x + threadIdx.x;
    if (idx >= NT3 * NK3) return;
    int t = idx / NK3, k = idx - t * NK3;
    int p = 0, rem = t;
    while (rem >= (II - p) * (II - p + 1) / 2) { rem -= (II - p) * (II - p + 1) / 2; p++; }
    int q = p;
    while (rem >= II - q) { rem -= II - q; q++; }
    int j = q + rem;

    float s;
    if (p == q && q == j) {
        s = U3AT(p, p, p);
    } else if (p == q) {
        s = U3AT(p, p, j) + U3AT(p, j, p) + U3AT(j, p, p);
    } else if (q == j) {
        s = U3AT(p, q, q) + U3AT(q, p, q) + U3AT(q, q, p);
    } else {
        s = U3AT(p, q, j) + U3AT(p, j, q) + U3AT(q, p, j) +
            U3AT(q, j, p) + U3AT(j, p, q) + U3AT(j, q, p);
    }
    g_P[t * NK3 + k] = s;
}

// ---------------- P1: per-channel coefficient build ----------------
__global__ void p1_kernel(const float* __restrict__ U2, const float* __restrict__ U1,
                          const float* __restrict__ w3, const float* __restrict__ w2,
                          const float* __restrict__ w1) {
    int c = blockIdx.x;
    int tid = threadIdx.x;
    __shared__ float w3s[NK3];
    __shared__ float w2s[NK2];
    __shared__ float w1s;
    if (tid < NK3) w3s[tid] = w3[c * NK3 + tid];
    if (tid < NK2) w2s[tid] = w2[c * NK2 + tid];
    if (tid == 0)  w1s = w1[c];
    __syncthreads();

    ull* cc = g_coeff + (size_t)c * 1024;

    for (int t = tid; t < NT3; t += blockDim.x) {
        float s = 0.f;
#pragma unroll
        for (int k = 0; k < NK3; k++) s += g_P[t * NK3 + k] * w3s[k];
        cc[t] = pk2(s, s);
    }
    for (int u = tid; u < NT2; u += blockDim.x) {
        int p = 0, rem = u;
        while (rem >= II - p) { rem -= II - p; p++; }
        int q = p + rem;
        float s = 0.f;
#pragma unroll
        for (int k = 0; k < NK2; k++) {
            float v = (p == q) ? U2[(p * II + p) * NK2 + k]
                               : (U2[(p * II + q) * NK2 + k] + U2[(q * II + p) * NK2 + k]);
            s += w2s[k] * v;
        }
        cc[NT3 + u] = pk2(s, s);
    }
    for (int p = tid; p < II; p += blockDim.x) {
        float s = U1[p] * w1s;  // K1 == 1
        cc[NT3 + NT2 + p] = pk2(s, s);
    }
}

// ---------------- Main: factored symmetric contraction, staged x, 4 b's/thread ----------------
#define XPAD 524
__global__ __launch_bounds__(128, 4) void main_kernel(const float* __restrict__ nf) {
    __shared__ ull   sco[NCOEFF];           // 7.75 KB
    __shared__ float xs[II][XPAD];          // 33.5 KB transposed x tile (512 b's)
    int c = blockIdx.y;
    int tid = threadIdx.x;
    {
        const ull* cc = g_coeff + (size_t)c * 1024;
        for (int i = tid; i < NCOEFF; i += 128) sco[i] = cc[i];
    }
    int bbase = blockIdx.x * 512;

#pragma unroll
    for (int it = 0; it < 16; it++) {
        int f = it * 128 + tid;
        int r = f >> 2, qd = f & 3;
        float4 v = *reinterpret_cast<const float4*>(
            &nf[((size_t)(bbase + r) * CI + c) * II + qd * 4]);
        xs[qd * 4 + 0][r] = v.x;
        xs[qd * 4 + 1][r] = v.y;
        xs[qd * 4 + 2][r] = v.z;
        xs[qd * 4 + 3][r] = v.w;
    }
    __syncthreads();

    int t4 = tid * 4;
    ull xA[II], xB[II];
#pragma unroll
    for (int i = 0; i < II; i++) {
        float4 v = *reinterpret_cast<const float4*>(&xs[i][t4]);
        xA[i] = pk2(v.x, v.y);
        xB[i] = pk2(v.z, v.w);
    }

    ull accA = 0ull, accB = 0ull;
    int s = 0, u = 0;
#pragma unroll
    for (int p = 0; p < II; p++) {
        ull c1v = sco[NT3 + NT2 + p];
        ull innerA = c1v, innerB = c1v;
#pragma unroll
        for (int q = p; q < II; q++) {
            ull c2v = sco[NT3 + u]; u++;
            ull pA = c2v, pB = c2v;
#pragma unroll
            for (int j = q; j < II; j++) {
                ull sv = sco[s]; s++;
                pA = fma2(xA[j], sv, pA);
                pB = fma2(xB[j], sv, pB);
            }
            innerA = fma2(xA[q], pA, innerA);
            innerB = fma2(xB[q], pB, innerB);
        }
        accA = fma2(xA[p], innerA, accA);
        accB = fma2(xB[p], innerB, accB);
    }

    float r0, r1, r2, r3;
    upk2(accA, r0, r1);
    upk2(accB, r2, r3);
    *reinterpret_cast<float4*>(&g_out1T[(size_t)c * BMAX + bbase + t4]) =
        make_float4(r0, r1, r2, r3);
}

// ---------------- convA: g_out1T -> fragment-ordered bf16 hi/lo (gAF) ----------------
// thread t = (kt[4b] | mt[8b] | lane[5b]); frag regs: i0:(k2=tig,m), i1:(tig,m+8),
// i2:(tig+4,m), i3:(tig+4,m+8) relative to (kt*8, mt*16+gid)
__global__ __launch_bounds__(128) void convA_kernel() {
    int t = blockIdx.x * 128 + threadIdx.x;    // 0 .. 131071
    int lane = t & 31;
    int mt = (t >> 5) & 255;
    int kt = t >> 13;
    int gid = lane >> 2, tig = lane & 3;
    int k2b = kt * 8;
    int m0 = mt * 16 + gid;
    int k2s[2] = {k2b + tig, k2b + 4 + tig};
    int ms[2]  = {m0, m0 + 8};
    unsigned int hi[4], lo[4];
#pragma unroll
    for (int i = 0; i < 4; i++) {
        int k2 = k2s[i >> 1];
        int mm = ms[i & 1];
        float v0 = g_out1T[(size_t)(2 * k2) * BMAX + mm];
        float v1 = g_out1T[(size_t)(2 * k2 + 1) * BMAX + mm];
        float r0, r1;
        hi[i] = packbf(v0, v1, r0, r1);
        lo[i] = packbf_only(r0, r1);
    }
    size_t base = (size_t)(kt * 256 + mt) * 256 + lane * 4;
    *reinterpret_cast<uint4*>(&gAF[base])       = make_uint4(hi[0], hi[1], hi[2], hi[3]);
    *reinterpret_cast<uint4*>(&gAF[base + 128]) = make_uint4(lo[0], lo[1], lo[2], lo[3]);
}

// ---------------- convB: W -> fragment-ordered bf16 hi/lo (gBF) ----------------
__global__ __launch_bounds__(128) void convB_kernel(const float* __restrict__ W) {
    int t = blockIdx.x * 128 + threadIdx.x;    // 0 .. 16383
    int lane = t & 31;
    int nt = (t >> 5) & 31;
    int kt = t >> 10;
    int gid = lane >> 2, tig = lane & 3;
    int k2b = kt * 8;
    int n = nt * 8 + gid;
    int k2s[2] = {k2b + tig, k2b + 4 + tig};
    unsigned int hi[2], lo[2];
#pragma unroll
    for (int i = 0; i < 2; i++) {
        int k2 = k2s[i];
        float v0 = W[(size_t)(2 * k2) * CI + n];
        float v1 = W[(size_t)(2 * k2 + 1) * CI + n];
        float r0, r1;
        hi[i] = packbf(v0, v1, r0, r1);
        lo[i] = packbf_only(r0, r1);
    }
    size_t base = (size_t)(kt * 32 + nt) * 128 + lane * 2;
    *reinterpret_cast<uint2*>(&gBF[base])      = make_uint2(hi[0], hi[1]);
    *reinterpret_cast<uint2*>(&gBF[base + 64]) = make_uint2(lo[0], lo[1]);
}

// ---------------- o3.Linear via mma.sync bf16x3, fragment-order wide loads ----------------
__global__ __launch_bounds__(128) void lin_mma_kernel(float* __restrict__ O) {
    int tid = threadIdx.x;
    int lane = tid & 31, wid = tid >> 5;
    int mtb = blockIdx.x * 2;            // two 16-row m-tiles per CTA
    int nt = blockIdx.y * 4 + wid;       // one 8-col n-tile per warp
    int gid = lane >> 2, tig = lane & 3;

    float acc[2][4] = {};

#pragma unroll 4
    for (int kt = 0; kt < 16; kt++) {
        size_t bb = (size_t)(kt * 32 + nt) * 128 + lane * 2;
        uint2 bhv = *reinterpret_cast<const uint2*>(&gBF[bb]);
        uint2 blv = *reinterpret_cast<const uint2*>(&gBF[bb + 64]);
        unsigned int bh[2] = {bhv.x, bhv.y};
        unsigned int bl[2] = {blv.x, blv.y};
#pragma unroll
        for (int mblk = 0; mblk < 2; mblk++) {
            size_t ab = (size_t)(kt * 256 + mtb + mblk) * 256 + lane * 4;
            uint4 ahv = *reinterpret_cast<const uint4*>(&gAF[ab]);
            uint4 alv = *reinterpret_cast<const uint4*>(&gAF[ab + 128]);
            unsigned int ah[4] = {ahv.x, ahv.y, ahv.z, ahv.w};
            unsigned int al[4] = {alv.x, alv.y, alv.z, alv.w};
            mma_bf16(acc[mblk], ah, bh);   // hi*hi
            mma_bf16(acc[mblk], ah, bl);   // hi*lo
            mma_bf16(acc[mblk], al, bh);   // lo*hi
        }
    }

    const float inv = 0.0625f;   // 1/sqrt(256)
#pragma unroll
    for (int mblk = 0; mblk < 2; mblk++) {
        int m = (mtb + mblk) * 16 + gid;
        int n = nt * 8 + tig * 2;
        *reinterpret_cast<float2*>(&O[(size_t)m * CI + n]) =
            make_float2(acc[mblk][0] * inv, acc[mblk][1] * inv);
        *reinterpret_cast<float2*>(&O[(size_t)(m + 8) * CI + n]) =
            make_float2(acc[mblk][2] * inv, acc[mblk][3] * inv);
    }
}

// ---------------- launch ----------------
extern "C" void kernel_launch(void* const* d_in, const int* in_sizes, int n_in,
                              void* d_out, int out_size) {
    const float* nf = (const float*)d_in[0];
    const float* U3 = (const float*)d_in[1];
    const float* U2 = (const float*)d_in[2];
    const float* U1 = (const float*)d_in[3];
    const float* w3 = (const float*)d_in[4];
    const float* w2 = (const float*)d_in[5];
    const float* w1 = (const float*)d_in[6];
    const float* WL = (const float*)d_in[7];
    float* out = (float*)d_out;

    int B = in_sizes[0] / (CI * II);   // 4096

    p0_kernel<<<(NT3 * NK3 + 255) / 256, 256>>>(U3);
    p1_kernel<<<CI, 128>>>(U2, U1, w3, w2, w1);
    convB_kernel<<<128, 128>>>(WL);                          // independent of main
    main_kernel<<<dim3(B / 512, CI), 128>>>(nf);
    convA_kernel<<<1024, 128>>>();
    lin_mma_kernel<<<dim3(B / 32, CI / 32), 128>>>(out);
}

// round 14
// speedup vs baseline: 1.2840x; 1.0510x over previous
#include <cuda_runtime.h>
#include <cuda_bf16.h>
#include <cstdint>

#define CI  256   // channels
#define II  16    // irrep dim
#define NK3 23
#define NK2 4
#define NT3 816   // C(18,3) sorted triples p<=q<=j
#define NT2 136   // sorted pairs p<=q
#define NCOEFF (NT3 + NT2 + II)   // 968
#define BMAX 4096

// ---------------- static device scratch (no allocation allowed) ----------------
__device__ float              g_P[NT3 * NK3];          // symmetrized U3 basis
__device__ unsigned long long g_coeff[CI * 1024];      // per-channel packed (v,v) coeffs
// mma-fragment-ordered operands (bf16x3 split):
// gAF: per (kt, mt): [hi 32 lanes x 4 u32][lo 32 lanes x 4 u32]
// gBF: per (kt, nt): [hi 32 lanes x 2 u32][lo 32 lanes x 2 u32]
__device__ unsigned int       gAF[16 * 256 * 256];
__device__ unsigned int       gBF[16 * 32 * 128];

typedef unsigned long long ull;

// ---------------- f32x2 packed-math helpers ----------------
__device__ __forceinline__ ull pk2(float lo, float hi) {
    ull r;
    asm("mov.b64 %0, {%1, %2};" : "=l"(r) : "f"(lo), "f"(hi));
    return r;
}
__device__ __forceinline__ void upk2(ull v, float& lo, float& hi) {
    asm("mov.b64 {%0, %1}, %2;" : "=f"(lo), "=f"(hi) : "l"(v));
}
__device__ __forceinline__ ull fma2(ull a, ull b, ull c) {
    ull d;
    asm("fma.rn.f32x2 %0, %1, %2, %3;" : "=l"(d) : "l"(a), "l"(b), "l"(c));
    return d;
}

// ---------------- bf16 helpers ----------------
__device__ __forceinline__ unsigned int packbf(float v0, float v1,
                                               float& r0, float& r1) {
    __nv_bfloat16 h0 = __float2bfloat16_rn(v0);
    __nv_bfloat16 h1 = __float2bfloat16_rn(v1);
    r0 = v0 - __bfloat162float(h0);
    r1 = v1 - __bfloat162float(h1);
    unsigned short u0 = *reinterpret_cast<unsigned short*>(&h0);
    unsigned short u1 = *reinterpret_cast<unsigned short*>(&h1);
    return (unsigned int)u0 | ((unsigned int)u1 << 16);
}
__device__ __forceinline__ unsigned int packbf_only(float v0, float v1) {
    __nv_bfloat16 h0 = __float2bfloat16_rn(v0);
    __nv_bfloat16 h1 = __float2bfloat16_rn(v1);
    unsigned short u0 = *reinterpret_cast<unsigned short*>(&h0);
    unsigned short u1 = *reinterpret_cast<unsigned short*>(&h1);
    return (unsigned int)u0 | ((unsigned int)u1 << 16);
}

// mma.sync m16n8k16 bf16
__device__ __forceinline__ void mma_bf16(float* c, const unsigned int* a,
                                         const unsigned int* b) {
    asm volatile(
        "mma.sync.aligned.m16n8k16.row.col.f32.bf16.bf16.f32 "
        "{%0,%1,%2,%3}, {%4,%5,%6,%7}, {%8,%9}, {%0,%1,%2,%3};"
        : "+f"(c[0]), "+f"(c[1]), "+f"(c[2]), "+f"(c[3])
        : "r"(a[0]), "r"(a[1]), "r"(a[2]), "r"(a[3]), "r"(b[0]), "r"(b[1]));
}

// ---------------- P0: symmetrize U3 over permutations -> g_P[t][k] ----------------
#define U3AT(a, b, d) U3[((((a) * II + (b)) * II + (d)) * NK3) + k]

__global__ void p0_kernel(const float* __restrict__ U3) {
    int idx = blockIdx.x * blockDim.x + threadIdx.x;
    if (idx >= NT3 * NK3) return;
    int t = idx / NK3, k = idx - t * NK3;
    int p = 0, rem = t;
    while (rem >= (II - p) * (II - p + 1) / 2) { rem -= (II - p) * (II - p + 1) / 2; p++; }
    int q = p;
    while (rem >= II - q) { rem -= II - q; q++; }
    int j = q + rem;

    float s;
    if (p == q && q == j) {
        s = U3AT(p, p, p);
    } else if (p == q) {
        s = U3AT(p, p, j) + U3AT(p, j, p) + U3AT(j, p, p);
    } else if (q == j) {
        s = U3AT(p, q, q) + U3AT(q, p, q) + U3AT(q, q, p);
    } else {
        s = U3AT(p, q, j) + U3AT(p, j, q) + U3AT(q, p, j) +
            U3AT(q, j, p) + U3AT(j, p, q) + U3AT(j, q, p);
    }
    g_P[t * NK3 + k] = s;
}

// ---------------- P1: per-channel coefficient build ----------------
__global__ void p1_kernel(const float* __restrict__ U2, const float* __restrict__ U1,
                          const float* __restrict__ w3, const float* __restrict__ w2,
                          const float* __restrict__ w1) {
    int c = blockIdx.x;
    int tid = threadIdx.x;
    __shared__ float w3s[NK3];
    __shared__ float w2s[NK2];
    __shared__ float w1s;
    if (tid < NK3) w3s[tid] = w3[c * NK3 + tid];
    if (tid < NK2) w2s[tid] = w2[c * NK2 + tid];
    if (tid == 0)  w1s = w1[c];
    __syncthreads();

    ull* cc = g_coeff + (size_t)c * 1024;

    for (int t = tid; t < NT3; t += blockDim.x) {
        float s = 0.f;
#pragma unroll
        for (int k = 0; k < NK3; k++) s += g_P[t * NK3 + k] * w3s[k];
        cc[t] = pk2(s, s);
    }
    for (int u = tid; u < NT2; u += blockDim.x) {
        int p = 0, rem = u;
        while (rem >= II - p) { rem -= II - p; p++; }
        int q = p + rem;
        float s = 0.f;
#pragma unroll
        for (int k = 0; k < NK2; k++) {
            float v = (p == q) ? U2[(p * II + p) * NK2 + k]
                               : (U2[(p * II + q) * NK2 + k] + U2[(q * II + p) * NK2 + k]);
            s += w2s[k] * v;
        }
        cc[NT3 + u] = pk2(s, s);
    }
    for (int p = tid; p < II; p += blockDim.x) {
        float s = U1[p] * w1s;  // K1 == 1
        cc[NT3 + NT2 + p] = pk2(s, s);
    }
}

// ---------------- Main: 2 channels x 256 b's per CTA, fused bf16 fragment epilogue ----------------
#define XPAD 260   // row stride (floats): mult of 4 for 16B align
__global__ __launch_bounds__(128, 4) void main_kernel(const float* __restrict__ nf) {
    __shared__ ull   sco[2][NCOEFF];        // 15.1 KB (both channels)
    __shared__ float xs[2][II][XPAD];       // 32.5 KB transposed x tiles (256 b's x 2 ch)
    // total static smem 48768 B <= 48 KB cap; outs[2][256] aliases xs after packing

    int cy = blockIdx.y;                    // channel pair index; c0 = 2*cy
    int c0 = cy * 2;
    int tid = threadIdx.x;
    int bbase = blockIdx.x * 256;

    {
        const ull* cc0 = g_coeff + (size_t)c0 * 1024;
        const ull* cc1 = g_coeff + (size_t)(c0 + 1) * 1024;
        for (int i = tid; i < NCOEFF; i += 128) {
            sco[0][i] = cc0[i];
            sco[1][i] = cc1[i];
        }
    }

    // cooperative x load: 256 b's x 2 ch x 16 floats; 128B contiguous per b
#pragma unroll
    for (int it = 0; it < 16; it++) {
        int f = it * 128 + tid;             // 0..2047
        int b = f >> 3;                     // 0..255
        int part = f & 7;                   // 8 float4 per b (2 ch x 4)
        int ch = part >> 2, qd = part & 3;
        float4 v = *reinterpret_cast<const float4*>(
            &nf[((size_t)(bbase + b) * CI + c0 + ch) * II + qd * 4]);
        xs[ch][qd * 4 + 0][b] = v.x;
        xs[ch][qd * 4 + 1][b] = v.y;
        xs[ch][qd * 4 + 2][b] = v.z;
        xs[ch][qd * 4 + 3][b] = v.w;
    }
    __syncthreads();

    // per-thread x: warp pair -> channel; 4 consecutive b's as 2 packed pairs
    int ch = tid >> 6;                      // warps 0-1 -> ch0, warps 2-3 -> ch1
    int tci = tid & 63;
    int t4 = tci * 4;
    ull xA[II], xB[II];
#pragma unroll
    for (int i = 0; i < II; i++) {
        float4 v = *reinterpret_cast<const float4*>(&xs[ch][i][t4]);
        xA[i] = pk2(v.x, v.y);
        xB[i] = pk2(v.z, v.w);
    }
    __syncthreads();    // xs now dead; safe to alias as outs below

    const ull* scoc = sco[ch];
    ull accA = 0ull, accB = 0ull;
    int s = 0, u = 0;
#pragma unroll
    for (int p = 0; p < II; p++) {
        ull c1v = scoc[NT3 + NT2 + p];
        ull innerA = c1v, innerB = c1v;
#pragma unroll
        for (int q = p; q < II; q++) {
            ull c2v = scoc[NT3 + u]; u++;
            ull pA = c2v, pB = c2v;
#pragma unroll
            for (int j = q; j < II; j++) {
                ull sv = scoc[s]; s++;
                pA = fma2(xA[j], sv, pA);
                pB = fma2(xB[j], sv, pB);
            }
            innerA = fma2(xA[q], pA, innerA);
            innerB = fma2(xB[q], pB, innerB);
        }
        accA = fma2(xA[p], innerA, accA);
        accB = fma2(xB[p], innerB, accB);
    }

    // stage outputs in smem (aliased onto xs), pair channels, emit bf16 fragments
    float* outs = reinterpret_cast<float*>(xs);    // layout [2][256]
    float r0, r1, r2, r3;
    upk2(accA, r0, r1);
    upk2(accB, r2, r3);
    outs[ch * 256 + t4 + 0] = r0;
    outs[ch * 256 + t4 + 1] = r1;
    outs[ch * 256 + t4 + 2] = r2;
    outs[ch * 256 + t4 + 3] = r3;
    __syncthreads();

    // fragment packing: k2 = cy; i = (khalf<<1)|mhalf; lane = gid*4+tig
    int kt = cy >> 3;
    int k2r = cy & 7;
    int tig = k2r & 3;
    int khalf = k2r >> 2;
#pragma unroll
    for (int mi = 0; mi < 2; mi++) {
        int m = tid * 2 + mi;               // 0..255 local
        float v0 = outs[m];                 // channel c0 (k even)
        float v1 = outs[256 + m];           // channel c0+1 (k odd)
        float q0, q1;
        unsigned int hi = packbf(v0, v1, q0, q1);
        unsigned int lo = packbf_only(q0, q1);
        int m_g = bbase + m;
        int mt = m_g >> 4;
        int mm = m_g & 15;
        int gid = mm & 7;
        int mhalf = mm >> 3;
        int i = khalf * 2 + mhalf;
        size_t idx = ((size_t)(kt * 256 + mt)) * 256 + (gid * 4 + tig) * 4 + i;
        gAF[idx] = hi;
        gAF[idx + 128] = lo;
    }
}

// ---------------- convB: W -> fragment-ordered bf16 hi/lo (gBF) ----------------
__global__ __launch_bounds__(128) void convB_kernel(const float* __restrict__ W) {
    int t = blockIdx.x * 128 + threadIdx.x;    // 0 .. 16383
    int lane = t & 31;
    int nt = (t >> 5) & 31;
    int kt = t >> 10;
    int gid = lane >> 2, tig = lane & 3;
    int k2b = kt * 8;
    int n = nt * 8 + gid;
    int k2s[2] = {k2b + tig, k2b + 4 + tig};
    unsigned int hi[2], lo[2];
#pragma unroll
    for (int i = 0; i < 2; i++) {
        int k2 = k2s[i];
        float v0 = W[(size_t)(2 * k2) * CI + n];
        float v1 = W[(size_t)(2 * k2 + 1) * CI + n];
        float r0, r1;
        hi[i] = packbf(v0, v1, r0, r1);
        lo[i] = packbf_only(r0, r1);
    }
    size_t base = (size_t)(kt * 32 + nt) * 128 + lane * 2;
    *reinterpret_cast<uint2*>(&gBF[base])      = make_uint2(hi[0], hi[1]);
    *reinterpret_cast<uint2*>(&gBF[base + 64]) = make_uint2(lo[0], lo[1]);
}

// ---------------- o3.Linear via mma.sync bf16x3, fragment-order wide loads ----------------
__global__ __launch_bounds__(128) void lin_mma_kernel(float* __restrict__ O) {
    int tid = threadIdx.x;
    int lane = tid & 31, wid = tid >> 5;
    int mtb = blockIdx.x * 2;            // two 16-row m-tiles per CTA
    int nt = blockIdx.y * 4 + wid;       // one 8-col n-tile per warp
    int gid = lane >> 2, tig = lane & 3;

    float acc[2][4] = {};

#pragma unroll 4
    for (int kt = 0; kt < 16; kt++) {
        size_t bb = (size_t)(kt * 32 + nt) * 128 + lane * 2;
        uint2 bhv = *reinterpret_cast<const uint2*>(&gBF[bb]);
        uint2 blv = *reinterpret_cast<const uint2*>(&gBF[bb + 64]);
        unsigned int bh[2] = {bhv.x, bhv.y};
        unsigned int bl[2] = {blv.x, blv.y};
#pragma unroll
        for (int mblk = 0; mblk < 2; mblk++) {
            size_t ab = (size_t)(kt * 256 + mtb + mblk) * 256 + lane * 4;
            uint4 ahv = *reinterpret_cast<const uint4*>(&gAF[ab]);
            uint4 alv = *reinterpret_cast<const uint4*>(&gAF[ab + 128]);
            unsigned int ah[4] = {ahv.x, ahv.y, ahv.z, ahv.w};
            unsigned int al[4] = {alv.x, alv.y, alv.z, alv.w};
            mma_bf16(acc[mblk], ah, bh);   // hi*hi
            mma_bf16(acc[mblk], ah, bl);   // hi*lo
            mma_bf16(acc[mblk], al, bh);   // lo*hi
        }
    }

    const float inv = 0.0625f;   // 1/sqrt(256)
#pragma unroll
    for (int mblk = 0; mblk < 2; mblk++) {
        int m = (mtb + mblk) * 16 + gid;
        int n = nt * 8 + tig * 2;
        *reinterpret_cast<float2*>(&O[(size_t)m * CI + n]) =
            make_float2(acc[mblk][0] * inv, acc[mblk][1] * inv);
        *reinterpret_cast<float2*>(&O[(size_t)(m + 8) * CI + n]) =
            make_float2(acc[mblk][2] * inv, acc[mblk][3] * inv);
    }
}

// ---------------- launch ----------------
extern "C" void kernel_launch(void* const* d_in, const int* in_sizes, int n_in,
                              void* d_out, int out_size) {
    const float* nf = (const float*)d_in[0];
    const float* U3 = (const float*)d_in[1];
    const float* U2 = (const float*)d_in[2];
    const float* U1 = (const float*)d_in[3];
    const float* w3 = (const float*)d_in[4];
    const float* w2 = (const float*)d_in[5];
    const float* w1 = (const float*)d_in[6];
    const float* WL = (const float*)d_in[7];
    float* out = (float*)d_out;

    int B = in_sizes[0] / (CI * II);   // 4096

    p0_kernel<<<(NT3 * NK3 + 255) / 256, 256>>>(U3);
    p1_kernel<<<CI, 128>>>(U2, U1, w3, w2, w1);
    convB_kernel<<<128, 128>>>(WL);                          // independent of main
    main_kernel<<<dim3(B / 256, CI / 2), 128>>>(nf);
    lin_mma_kernel<<<dim3(B / 32, CI / 32), 128>>>(out);
}

// round 17
// speedup vs baseline: 1.3122x; 1.0220x over previous
#include <cuda_runtime.h>
#include <cuda_bf16.h>
#include <cstdint>

#define CI  256   // channels
#define II  16    // irrep dim
#define NK3 23
#define NK2 4
#define NT3 816   // C(18,3) sorted triples p<=q<=j
#define NT2 136   // sorted pairs p<=q
#define NCOEFF (NT3 + NT2 + II)   // 968
#define BMAX 4096

// ---------------- static device scratch (no allocation allowed) ----------------
__device__ float              g_P[NT3 * NK3];          // symmetrized U3 basis
__device__ unsigned long long g_coeff[CI * 1024];      // per-channel packed (v,v) coeffs
// mma-fragment-ordered operands (bf16x3 split):
// gAF: per (kt, mt): [hi 32 lanes x 4 u32][lo 32 lanes x 4 u32]
// gBF: per (kt, nt): [hi 32 lanes x 2 u32][lo 32 lanes x 2 u32]
__device__ unsigned int       gAF[16 * 256 * 256];
__device__ unsigned int       gBF[16 * 32 * 128];

typedef unsigned long long ull;

// ---------------- f32x2 packed-math helpers ----------------
__device__ __forceinline__ ull pk2(float lo, float hi) {
    ull r;
    asm("mov.b64 %0, {%1, %2};" : "=l"(r) : "f"(lo), "f"(hi));
    return r;
}
__device__ __forceinline__ void upk2(ull v, float& lo, float& hi) {
    asm("mov.b64 {%0, %1}, %2;" : "=f"(lo), "=f"(hi) : "l"(v));
}
__device__ __forceinline__ ull fma2(ull a, ull b, ull c) {
    ull d;
    asm("fma.rn.f32x2 %0, %1, %2, %3;" : "=l"(d) : "l"(a), "l"(b), "l"(c));
    return d;
}

// ---------------- bf16 helpers ----------------
__device__ __forceinline__ unsigned int packbf(float v0, float v1,
                                               float& r0, float& r1) {
    __nv_bfloat16 h0 = __float2bfloat16_rn(v0);
    __nv_bfloat16 h1 = __float2bfloat16_rn(v1);
    r0 = v0 - __bfloat162float(h0);
    r1 = v1 - __bfloat162float(h1);
    unsigned short u0 = *reinterpret_cast<unsigned short*>(&h0);
    unsigned short u1 = *reinterpret_cast<unsigned short*>(&h1);
    return (unsigned int)u0 | ((unsigned int)u1 << 16);
}
__device__ __forceinline__ unsigned int packbf_only(float v0, float v1) {
    __nv_bfloat16 h0 = __float2bfloat16_rn(v0);
    __nv_bfloat16 h1 = __float2bfloat16_rn(v1);
    unsigned short u0 = *reinterpret_cast<unsigned short*>(&h0);
    unsigned short u1 = *reinterpret_cast<unsigned short*>(&h1);
    return (unsigned int)u0 | ((unsigned int)u1 << 16);
}

// mma.sync m16n8k16 bf16
__device__ __forceinline__ void mma_bf16(float* c, const unsigned int* a,
                                         const unsigned int* b) {
    asm volatile(
        "mma.sync.aligned.m16n8k16.row.col.f32.bf16.bf16.f32 "
        "{%0,%1,%2,%3}, {%4,%5,%6,%7}, {%8,%9}, {%0,%1,%2,%3};"
        : "+f"(c[0]), "+f"(c[1]), "+f"(c[2]), "+f"(c[3])
        : "r"(a[0]), "r"(a[1]), "r"(a[2]), "r"(a[3]), "r"(b[0]), "r"(b[1]));
}

// ---------------- prep: p0 (symmetrize U3) + convB (W -> gBF) fused, branch on block ----------------
#define U3AT(a, b, d) U3[((((a) * II + (b)) * II + (d)) * NK3) + k]
#define P0_BLOCKS 74   // 74*256 >= NT3*NK3 = 18768

__global__ __launch_bounds__(256) void prep_kernel(const float* __restrict__ U3,
                                                   const float* __restrict__ W) {
    if (blockIdx.x < P0_BLOCKS) {
        // ---- p0 body ----
        int idx = blockIdx.x * 256 + threadIdx.x;
        if (idx >= NT3 * NK3) return;
        int t = idx / NK3, k = idx - t * NK3;
        int p = 0, rem = t;
        while (rem >= (II - p) * (II - p + 1) / 2) { rem -= (II - p) * (II - p + 1) / 2; p++; }
        int q = p;
        while (rem >= II - q) { rem -= II - q; q++; }
        int j = q + rem;

        float s;
        if (p == q && q == j) {
            s = U3AT(p, p, p);
        } else if (p == q) {
            s = U3AT(p, p, j) + U3AT(p, j, p) + U3AT(j, p, p);
        } else if (q == j) {
            s = U3AT(p, q, q) + U3AT(q, p, q) + U3AT(q, q, p);
        } else {
            s = U3AT(p, q, j) + U3AT(p, j, q) + U3AT(q, p, j) +
                U3AT(q, j, p) + U3AT(j, p, q) + U3AT(j, q, p);
        }
        g_P[t * NK3 + k] = s;
    } else {
        // ---- convB body: W -> fragment-ordered bf16 hi/lo (gBF) ----
        int t = (blockIdx.x - P0_BLOCKS) * 256 + threadIdx.x;   // 0 .. 16383
        int lane = t & 31;
        int nt = (t >> 5) & 31;
        int kt = t >> 10;
        int gid = lane >> 2, tig = lane & 3;
        int k2b = kt * 8;
        int n = nt * 8 + gid;
        int k2s[2] = {k2b + tig, k2b + 4 + tig};
        unsigned int hi[2], lo[2];
#pragma unroll
        for (int i = 0; i < 2; i++) {
            int k2 = k2s[i];
            float v0 = W[(size_t)(2 * k2) * CI + n];
            float v1 = W[(size_t)(2 * k2 + 1) * CI + n];
            float r0, r1;
            hi[i] = packbf(v0, v1, r0, r1);
            lo[i] = packbf_only(r0, r1);
        }
        size_t base = (size_t)(kt * 32 + nt) * 128 + lane * 2;
        *reinterpret_cast<uint2*>(&gBF[base])      = make_uint2(hi[0], hi[1]);
        *reinterpret_cast<uint2*>(&gBF[base + 64]) = make_uint2(lo[0], lo[1]);
    }
}

// ---------------- P1: per-channel coefficient build ----------------
__global__ void p1_kernel(const float* __restrict__ U2, const float* __restrict__ U1,
                          const float* __restrict__ w3, const float* __restrict__ w2,
                          const float* __restrict__ w1) {
    int c = blockIdx.x;
    int tid = threadIdx.x;
    __shared__ float w3s[NK3];
    __shared__ float w2s[NK2];
    __shared__ float w1s;
    if (tid < NK3) w3s[tid] = w3[c * NK3 + tid];
    if (tid < NK2) w2s[tid] = w2[c * NK2 + tid];
    if (tid == 0)  w1s = w1[c];
    __syncthreads();

    ull* cc = g_coeff + (size_t)c * 1024;

    for (int t = tid; t < NT3; t += blockDim.x) {
        float s = 0.f;
#pragma unroll
        for (int k = 0; k < NK3; k++) s += g_P[t * NK3 + k] * w3s[k];
        cc[t] = pk2(s, s);
    }
    for (int u = tid; u < NT2; u += blockDim.x) {
        int p = 0, rem = u;
        while (rem >= II - p) { rem -= II - p; p++; }
        int q = p + rem;
        float s = 0.f;
#pragma unroll
        for (int k = 0; k < NK2; k++) {
            float v = (p == q) ? U2[(p * II + p) * NK2 + k]
                               : (U2[(p * II + q) * NK2 + k] + U2[(q * II + p) * NK2 + k]);
            s += w2s[k] * v;
        }
        cc[NT3 + u] = pk2(s, s);
    }
    for (int p = tid; p < II; p += blockDim.x) {
        float s = U1[p] * w1s;  // K1 == 1
        cc[NT3 + NT2 + p] = pk2(s, s);
    }
}

// ---------------- Main: 2 channels x 256 b's per CTA, fused bf16 fragment epilogue ----------------
#define XPAD 260   // row stride (floats): mult of 4 for 16B align
__global__ __launch_bounds__(128, 4) void main_kernel(const float* __restrict__ nf) {
    __shared__ ull   sco[2][NCOEFF];        // 15.1 KB (both channels)
    __shared__ float xs[2][II][XPAD];       // 32.5 KB transposed x tiles (256 b's x 2 ch)

    int cy = blockIdx.y;                    // channel pair index; c0 = 2*cy
    int c0 = cy * 2;
    int tid = threadIdx.x;
    int bbase = blockIdx.x * 256;

    {
        const ull* cc0 = g_coeff + (size_t)c0 * 1024;
        const ull* cc1 = g_coeff + (size_t)(c0 + 1) * 1024;
        for (int i = tid; i < NCOEFF; i += 128) {
            sco[0][i] = cc0[i];
            sco[1][i] = cc1[i];
        }
    }

    // cooperative x load: 256 b's x 2 ch x 16 floats; 128B contiguous per b
#pragma unroll
    for (int it = 0; it < 16; it++) {
        int f = it * 128 + tid;             // 0..2047
        int b = f >> 3;                     // 0..255
        int part = f & 7;                   // 8 float4 per b (2 ch x 4)
        int ch = part >> 2, qd = part & 3;
        float4 v = *reinterpret_cast<const float4*>(
            &nf[((size_t)(bbase + b) * CI + c0 + ch) * II + qd * 4]);
        xs[ch][qd * 4 + 0][b] = v.x;
        xs[ch][qd * 4 + 1][b] = v.y;
        xs[ch][qd * 4 + 2][b] = v.z;
        xs[ch][qd * 4 + 3][b] = v.w;
    }
    __syncthreads();

    // per-thread x: warp pair -> channel; 4 consecutive b's as 2 packed pairs
    int ch = tid >> 6;                      // warps 0-1 -> ch0, warps 2-3 -> ch1
    int tci = tid & 63;
    int t4 = tci * 4;
    ull xA[II], xB[II];
#pragma unroll
    for (int i = 0; i < II; i++) {
        float4 v = *reinterpret_cast<const float4*>(&xs[ch][i][t4]);
        xA[i] = pk2(v.x, v.y);
        xB[i] = pk2(v.z, v.w);
    }
    __syncthreads();    // xs now dead; safe to alias as outs below

    const ull* scoc = sco[ch];
    ull accA = 0ull, accB = 0ull;
    int s = 0, u = 0;
#pragma unroll
    for (int p = 0; p < II; p++) {
        ull c1v = scoc[NT3 + NT2 + p];
        ull innerA = c1v, innerB = c1v;
#pragma unroll
        for (int q = p; q < II; q++) {
            ull c2v = scoc[NT3 + u]; u++;
            ull pA = c2v, pB = c2v;
#pragma unroll
            for (int j = q; j < II; j++) {
                ull sv = scoc[s]; s++;
                pA = fma2(xA[j], sv, pA);
                pB = fma2(xB[j], sv, pB);
            }
            innerA = fma2(xA[q], pA, innerA);
            innerB = fma2(xB[q], pB, innerB);
        }
        accA = fma2(xA[p], innerA, accA);
        accB = fma2(xB[p], innerB, accB);
    }

    // stage outputs in smem (aliased onto xs), pair channels, emit bf16 fragments
    float* outs = reinterpret_cast<float*>(xs);    // layout [2][256]
    float r0, r1, r2, r3;
    upk2(accA, r0, r1);
    upk2(accB, r2, r3);
    outs[ch * 256 + t4 + 0] = r0;
    outs[ch * 256 + t4 + 1] = r1;
    outs[ch * 256 + t4 + 2] = r2;
    outs[ch * 256 + t4 + 3] = r3;
    __syncthreads();

    // fragment packing: k2 = cy; i = (khalf<<1)|mhalf; lane = gid*4+tig
    int kt = cy >> 3;
    int k2r = cy & 7;
    int tig = k2r & 3;
    int khalf = k2r >> 2;
#pragma unroll
    for (int mi = 0; mi < 2; mi++) {
        int m = tid * 2 + mi;               // 0..255 local
        float v0 = outs[m];                 // channel c0 (k even)
        float v1 = outs[256 + m];           // channel c0+1 (k odd)
        float q0, q1;
        unsigned int hi = packbf(v0, v1, q0, q1);
        unsigned int lo = packbf_only(q0, q1);
        int m_g = bbase + m;
        int mt = m_g >> 4;
        int mm = m_g & 15;
        int gid = mm & 7;
        int mhalf = mm >> 3;
        int i = khalf * 2 + mhalf;
        size_t idx = ((size_t)(kt * 256 + mt)) * 256 + (gid * 4 + tig) * 4 + i;
        gAF[idx] = hi;
        gAF[idx + 128] = lo;
    }
}

// ---------------- o3.Linear via mma.sync bf16x3, register double-buffered pipeline ----------------
__global__ __launch_bounds__(128) void lin_mma_kernel(float* __restrict__ O) {
    int tid = threadIdx.x;
    int lane = tid & 31, wid = tid >> 5;
    int mtb = blockIdx.x * 2;            // two 16-row m-tiles per CTA
    int nt = blockIdx.y * 4 + wid;       // one 8-col n-tile per warp
    int gid = lane >> 2, tig = lane & 3;

    float acc[2][4] = {};

    // double-buffered fragments
    uint2 bhv[2], blv[2];
    uint4 ahv[2][2], alv[2][2];

    // prologue: load kt = 0 into buffer 0
    {
        size_t bb = (size_t)(0 * 32 + nt) * 128 + lane * 2;
        bhv[0] = *reinterpret_cast<const uint2*>(&gBF[bb]);
        blv[0] = *reinterpret_cast<const uint2*>(&gBF[bb + 64]);
#pragma unroll
        for (int mblk = 0; mblk < 2; mblk++) {
            size_t ab = (size_t)(0 * 256 + mtb + mblk) * 256 + lane * 4;
            ahv[0][mblk] = *reinterpret_cast<const uint4*>(&gAF[ab]);
            alv[0][mblk] = *reinterpret_cast<const uint4*>(&gAF[ab + 128]);
        }
    }

#pragma unroll
    for (int kt = 0; kt < 16; kt++) {
        const int cur = kt & 1, nxt = cur ^ 1;
        if (kt < 15) {   // prefetch kt+1 while computing kt
            size_t bb = (size_t)((kt + 1) * 32 + nt) * 128 + lane * 2;
            bhv[nxt] = *reinterpret_cast<const uint2*>(&gBF[bb]);
            blv[nxt] = *reinterpret_cast<const uint2*>(&gBF[bb + 64]);
#pragma unroll
            for (int mblk = 0; mblk < 2; mblk++) {
                size_t ab = (size_t)((kt + 1) * 256 + mtb + mblk) * 256 + lane * 4;
                ahv[nxt][mblk] = *reinterpret_cast<const uint4*>(&gAF[ab]);
                alv[nxt][mblk] = *reinterpret_cast<const uint4*>(&gAF[ab + 128]);
            }
        }
        unsigned int bh[2] = {bhv[cur].x, bhv[cur].y};
        unsigned int bl[2] = {blv[cur].x, blv[cur].y};
#pragma unroll
        for (int mblk = 0; mblk < 2; mblk++) {
            unsigned int ah[4] = {ahv[cur][mblk].x, ahv[cur][mblk].y,
                                  ahv[cur][mblk].z, ahv[cur][mblk].w};
            unsigned int al[4] = {alv[cur][mblk].x, alv[cur][mblk].y,
                                  alv[cur][mblk].z, alv[cur][mblk].w};
            mma_bf16(acc[mblk], ah, bh);   // hi*hi
            mma_bf16(acc[mblk], ah, bl);   // hi*lo
            mma_bf16(acc[mblk], al, bh);   // lo*hi
        }
    }

    const float inv = 0.0625f;   // 1/sqrt(256)
#pragma unroll
    for (int mblk = 0; mblk < 2; mblk++) {
        int m = (mtb + mblk) * 16 + gid;
        int n = nt * 8 + tig * 2;
        *reinterpret_cast<float2*>(&O[(size_t)m * CI + n]) =
            make_float2(acc[mblk][0] * inv, acc[mblk][1] * inv);
        *reinterpret_cast<float2*>(&O[(size_t)(m + 8) * CI + n]) =
            make_float2(acc[mblk][2] * inv, acc[mblk][3] * inv);
    }
}

// ---------------- launch ----------------
extern "C" void kernel_launch(void* const* d_in, const int* in_sizes, int n_in,
                              void* d_out, int out_size) {
    const float* nf = (const float*)d_in[0];
    const float* U3 = (const float*)d_in[1];
    const float* U2 = (const float*)d_in[2];
    const float* U1 = (const float*)d_in[3];
    const float* w3 = (const float*)d_in[4];
    const float* w2 = (const float*)d_in[5];
    const float* w1 = (const float*)d_in[6];
    const float* WL = (const float*)d_in[7];
    float* out = (float*)d_out;

    int B = in_sizes[0] / (CI * II);   // 4096

    prep_kernel<<<P0_BLOCKS + 64, 256>>>(U3, WL);   // p0 + convB fused
    p1_kernel<<<CI, 128>>>(U2, U1, w3, w2, w1);
    main_kernel<<<dim3(B / 256, CI / 2), 128>>>(nf);
    lin_mma_kernel<<<dim3(B / 32, CI / 32), 128>>>(out);
}